// round 12
// baseline (speedup 1.0000x reference)
#include <cuda_runtime.h>
#include <cuda_fp16.h>
#include <cstdint>

#define GCN_N     100000
#define GCN_NNZ   3200000
#define GCN_SLOPE 0.25f
#define CH        25088                       // M-chunk (divisible by 128 and 8)

// ---------------- device scratch (static, allocation-free) ----------------
__device__ __align__(16) int    g_rowptr[GCN_N + 1];
__device__ __align__(16) int    g_cursor[GCN_N];
__device__ __align__(16) int    g_cnt[GCN_N];
__device__ __align__(16) int    g_bsum[512];
__device__ __align__(16) uint2  g_scv[GCN_NNZ];
__device__ __align__(16) __half g_supA[(size_t)GCN_N * 256];
__device__ __align__(16) __half g_supB[(size_t)GCN_N * 256];
__device__ __align__(16) __half g_a[(size_t)GCN_N * 512];
__device__ __align__(16) __half g_b1[256 * 512];
__device__ __align__(16) __half g_b2[256 * 256];
__device__ __align__(16) __half g_b3[128 * 256];

// ---------------- CSR build ----------------
__global__ void zero_kernel(int* p, int n) {
    int i = blockIdx.x * blockDim.x + threadIdx.x;
    if (i < n) p[i] = 0;
}
__global__ void hist_kernel(const int* __restrict__ rows, int* __restrict__ counts, int nnz) {
    int i = blockIdx.x * blockDim.x + threadIdx.x;
    if (i < nnz) atomicAdd(&counts[rows[i]], 1);
}
__global__ void scanA_kernel(const int* __restrict__ counts, int* __restrict__ rowptr,
                             int* __restrict__ bsum, int n) {
    __shared__ int ws[8];
    int i = blockIdx.x * 256 + threadIdx.x;
    int lane = threadIdx.x & 31, w = threadIdx.x >> 5;
    int v = (i < n) ? counts[i] : 0;
    int x = v;
    #pragma unroll
    for (int d = 1; d < 32; d <<= 1) {
        int y = __shfl_up_sync(0xffffffffu, x, d);
        if (lane >= d) x += y;
    }
    if (lane == 31) ws[w] = x;
    __syncthreads();
    if (w == 0) {
        int t = (lane < 8) ? ws[lane] : 0;
        #pragma unroll
        for (int d = 1; d < 8; d <<= 1) {
            int y = __shfl_up_sync(0xffffffffu, t, d);
            if (lane >= d) t += y;
        }
        if (lane < 8) ws[lane] = t;
    }
    __syncthreads();
    int incl = x + (w > 0 ? ws[w - 1] : 0);
    if (i < n) rowptr[i + 1] = incl;
    if (threadIdx.x == 255) bsum[blockIdx.x] = incl;
}
__global__ void scanB_kernel(int* __restrict__ bsum, int nb) {
    __shared__ int ws[16];
    int i = threadIdx.x, lane = i & 31, w = i >> 5;
    int v = (i < nb) ? bsum[i] : 0;
    int x = v;
    #pragma unroll
    for (int d = 1; d < 32; d <<= 1) {
        int y = __shfl_up_sync(0xffffffffu, x, d);
        if (lane >= d) x += y;
    }
    if (lane == 31) ws[w] = x;
    __syncthreads();
    if (w == 0) {
        int t = (lane < 16) ? ws[lane] : 0;
        #pragma unroll
        for (int d = 1; d < 16; d <<= 1) {
            int y = __shfl_up_sync(0xffffffffu, t, d);
            if (lane >= d) t += y;
        }
        if (lane < 16) ws[lane] = t;
    }
    __syncthreads();
    int incl = x + (w > 0 ? ws[w - 1] : 0);
    if (i < nb) bsum[i] = incl - v;
}
__global__ void scanC_kernel(const int* __restrict__ counts, const int* __restrict__ bsum,
                             int* __restrict__ rowptr, int* __restrict__ cursor, int n) {
    int i = blockIdx.x * 256 + threadIdx.x;
    if (i < n) {
        int incl = rowptr[i + 1] + bsum[blockIdx.x];
        rowptr[i + 1] = incl;
        cursor[i] = incl - counts[i];
    }
    if (i == 0) rowptr[0] = 0;
}
__global__ void scatter_kernel(const int* __restrict__ rows, const int* __restrict__ cols,
                               const float* __restrict__ vals, int* __restrict__ cursor,
                               uint2* __restrict__ scv, int nnz) {
    int i = blockIdx.x * blockDim.x + threadIdx.x;
    if (i < nnz) {
        int r = rows[i];
        int pos = atomicAdd(&cursor[r], 1);
        scv[pos] = make_uint2((unsigned)cols[i], __float_as_uint(vals[i]));
    }
}

// x fp32 -> fp16 (per-chunk)
__global__ void convert_x(const float* __restrict__ in, __half* __restrict__ outh, int n4) {
    int i = blockIdx.x * blockDim.x + threadIdx.x;
    if (i >= n4) return;
    float4 v = __ldg((const float4*)in + i);
    ((__half2*)outh)[2 * i]     = __floats2half2_rn(v.x, v.y);
    ((__half2*)outh)[2 * i + 1] = __floats2half2_rn(v.z, v.w);
}

// W[K,N] -> B[n,k] fp16 (transpose)
__global__ void wsplit_single(const float* __restrict__ W, __half* __restrict__ bp,
                              int K, int N) {
    int idx = blockIdx.x * blockDim.x + threadIdx.x;
    if (idx >= K * N) return;
    int k = idx / N, n = idx % N;
    bp[(size_t)n * K + k] = __float2half_rn(W[idx]);
}

// ---------------- fp16 GEMM via mma.sync, cp.async -------------------------
__global__ __launch_bounds__(256) void gemm_mma(const __half* __restrict__ A,
                                                const __half* __restrict__ B,
                                                __half* __restrict__ C,
                                                int M, int N, int K) {
    extern __shared__ char smem[];
    constexpr int STAGES = 3;
    constexpr int ABYTES = 128 * 64 * 2;
    constexpr int BBYTES = 128 * 64 * 2;
    uint32_t sa_base;
    asm("{ .reg .u64 t; cvta.to.shared.u64 t, %1; cvt.u32.u64 %0, t; }" : "=r"(sa_base) : "l"(smem));
    uint32_t sb_base = sa_base + STAGES * ABYTES;

    int tid = threadIdx.x;
    int wid = tid >> 5, lane = tid & 31;
    int wm = wid & 3, wn = wid >> 2;
    int m0 = blockIdx.y * 128, n0 = blockIdx.x * 128;
    int NC = K / 64;

    float d[2][8][4];
    #pragma unroll
    for (int mi = 0; mi < 2; mi++)
        #pragma unroll
        for (int nj = 0; nj < 8; nj++)
            #pragma unroll
            for (int q = 0; q < 4; q++) d[mi][nj][q] = 0.f;

    const __half* Abase = A + (size_t)m0 * K;
    const __half* Bbase = B + (size_t)n0 * K;

#define LOAD_STAGE(st, ch) do {                                                   \
        uint32_t _da = sa_base + (st) * ABYTES;                                   \
        uint32_t _db = sb_base + (st) * BBYTES;                                   \
        int _k0 = (ch) * 64;                                                      \
        _Pragma("unroll")                                                         \
        for (int _i = 0; _i < 4; _i++) {                                          \
            int _u = tid + _i * 256;                                              \
            int _r = _u >> 3, _c = _u & 7;                                        \
            uint32_t _off = (uint32_t)(_r * 128 + _c * 16);                       \
            _off ^= ((_off >> 3) & 0x70);                                         \
            const __half* _src = Abase + (size_t)_r * K + _k0 + _c * 8;           \
            uint32_t _sz = (m0 + _r < M) ? 16u : 0u;                              \
            if (m0 + _r >= M) _src = Abase + _k0;                                 \
            asm volatile("cp.async.cg.shared.global [%0], [%1], 16, %2;"          \
                :: "r"(_da + _off), "l"(_src), "r"(_sz));                         \
        }                                                                         \
        _Pragma("unroll")                                                         \
        for (int _i = 0; _i < 4; _i++) {                                          \
            int _u = tid + _i * 256;                                              \
            int _r = _u >> 3, _c = _u & 7;                                        \
            uint32_t _off = (uint32_t)(_r * 128 + _c * 16);                       \
            _off ^= ((_off >> 3) & 0x70);                                         \
            const __half* _src = Bbase + (size_t)_r * K + _k0 + _c * 8;           \
            asm volatile("cp.async.cg.shared.global [%0], [%1], 16;"              \
                :: "r"(_db + _off), "l"(_src));                                   \
        }                                                                         \
    } while (0)

    LOAD_STAGE(0, 0);
    asm volatile("cp.async.commit_group;");
    if (NC > 1) LOAD_STAGE(1, 1);
    asm volatile("cp.async.commit_group;");

    for (int c = 0; c < NC; c++) {
        asm volatile("cp.async.wait_group 1;");
        __syncthreads();
        if (c + 2 < NC) LOAD_STAGE((c + 2) % STAGES, c + 2);
        asm volatile("cp.async.commit_group;");

        uint32_t da = sa_base + (c % STAGES) * ABYTES;
        uint32_t db = sb_base + (c % STAGES) * BBYTES;
        #pragma unroll
        for (int kk = 0; kk < 4; kk++) {
            int k16 = kk * 16;
            uint32_t a[2][4];
            #pragma unroll
            for (int mi = 0; mi < 2; mi++) {
                int row = wm * 32 + mi * 16 + (lane & 15);
                int colB = (k16 + ((lane >> 4) << 3)) * 2;
                uint32_t off = (uint32_t)(row * 128 + colB);
                off ^= ((off >> 3) & 0x70);
                asm volatile("ldmatrix.sync.aligned.m8n8.x4.shared.b16 {%0,%1,%2,%3}, [%4];"
                    : "=r"(a[mi][0]), "=r"(a[mi][1]), "=r"(a[mi][2]), "=r"(a[mi][3])
                    : "r"(da + off));
            }
            uint32_t b[8][2];
            #pragma unroll
            for (int nj = 0; nj < 4; nj++) {
                int nrow = wn * 64 + nj * 16 + (lane & 7) + ((lane >> 4) << 3);
                int colB = (k16 + (((lane >> 3) & 1) << 3)) * 2;
                uint32_t off = (uint32_t)(nrow * 128 + colB);
                off ^= ((off >> 3) & 0x70);
                uint32_t r0, r1, r2, r3;
                asm volatile("ldmatrix.sync.aligned.m8n8.x4.shared.b16 {%0,%1,%2,%3}, [%4];"
                    : "=r"(r0), "=r"(r1), "=r"(r2), "=r"(r3) : "r"(db + off));
                b[nj * 2][0] = r0; b[nj * 2][1] = r1;
                b[nj * 2 + 1][0] = r2; b[nj * 2 + 1][1] = r3;
            }
            #pragma unroll
            for (int mi = 0; mi < 2; mi++)
                #pragma unroll
                for (int nj = 0; nj < 8; nj++)
                    asm volatile("mma.sync.aligned.m16n8k16.row.col.f32.f16.f16.f32 "
                        "{%0,%1,%2,%3}, {%4,%5,%6,%7}, {%8,%9}, {%0,%1,%2,%3};"
                        : "+f"(d[mi][nj][0]), "+f"(d[mi][nj][1]),
                          "+f"(d[mi][nj][2]), "+f"(d[mi][nj][3])
                        : "r"(a[mi][0]), "r"(a[mi][1]), "r"(a[mi][2]), "r"(a[mi][3]),
                          "r"(b[nj][0]), "r"(b[nj][1]));
        }
        __syncthreads();
    }
#undef LOAD_STAGE

    #pragma unroll
    for (int mi = 0; mi < 2; mi++) {
        int r0 = m0 + wm * 32 + mi * 16 + (lane >> 2);
        #pragma unroll
        for (int nj = 0; nj < 8; nj++) {
            int col = n0 + wn * 64 + nj * 8 + 2 * (lane & 3);
            if (r0 < M)
                *(__half2*)(C + (size_t)r0 * N + col) =
                    __floats2half2_rn(d[mi][nj][0], d[mi][nj][1]);
            if (r0 + 8 < M)
                *(__half2*)(C + (size_t)(r0 + 8) * N + col) =
                    __floats2half2_rn(d[mi][nj][2], d[mi][nj][3]);
        }
    }
}

// ---------------- SpMM (fp16 gather, packed edges) + bias + leaky ----------
// processes rows [row0, row0+nrows)
template <int D, bool HALF_OUT>
__global__ __launch_bounds__(256) void spmm_kernel(const __half* __restrict__ sup,
                                                   const uint2* __restrict__ scv,
                                                   const int* __restrict__ rowptr,
                                                   const float* __restrict__ bias,
                                                   float* __restrict__ outf,
                                                   __half* __restrict__ outa,
                                                   int row0, int nrows) {
    int warp = (blockIdx.x * blockDim.x + threadIdx.x) >> 5;
    int lane = threadIdx.x & 31;
    if (warp >= nrows) return;
    int row = row0 + warp;
    int s = rowptr[row];
    int e = rowptr[row + 1];
    constexpr int VEC = D / 32;
    float acc[VEC];
    #pragma unroll
    for (int q = 0; q < VEC; q++) acc[q] = 0.f;

    const int lanecol = lane * VEC;

#define GATHER(cc, vv) do {                                                        \
        const __half* _b = sup + (size_t)(cc) * D + lanecol;                       \
        if (VEC == 8) {                                                            \
            uint4 _r = __ldg((const uint4*)_b);                                    \
            const __half2* _h = (const __half2*)&_r;                               \
            _Pragma("unroll")                                                      \
            for (int _q = 0; _q < 4; _q++) {                                       \
                float2 _f = __half22float2(_h[_q]);                                \
                acc[2 * _q]     += (vv) * _f.x;                                    \
                acc[2 * _q + 1] += (vv) * _f.y;                                    \
            }                                                                      \
        } else {                                                                   \
            uint2 _r = __ldg((const uint2*)_b);                                    \
            const __half2* _h = (const __half2*)&_r;                               \
            _Pragma("unroll")                                                      \
            for (int _q = 0; _q < 2; _q++) {                                       \
                float2 _f = __half22float2(_h[_q]);                                \
                acc[2 * _q]     += (vv) * _f.x;                                    \
                acc[2 * _q + 1] += (vv) * _f.y;                                    \
            }                                                                      \
        }                                                                          \
    } while (0)

    int p = s;
    for (; p + 3 < e; p += 4) {
        uint2 e0 = __ldg(&scv[p]),     e1 = __ldg(&scv[p + 1]);
        uint2 e2 = __ldg(&scv[p + 2]), e3 = __ldg(&scv[p + 3]);
        GATHER(e0.x, __uint_as_float(e0.y));
        GATHER(e1.x, __uint_as_float(e1.y));
        GATHER(e2.x, __uint_as_float(e2.y));
        GATHER(e3.x, __uint_as_float(e3.y));
    }
    for (; p < e; p++) {
        uint2 ee = __ldg(&scv[p]);
        GATHER(ee.x, __uint_as_float(ee.y));
    }
#undef GATHER

    float r[VEC];
    #pragma unroll
    for (int q = 0; q < VEC; q += 4) {
        float4 b = __ldg((const float4*)(bias + lanecol + q));
        r[q]     = acc[q]     + b.x;
        r[q + 1] = acc[q + 1] + b.y;
        r[q + 2] = acc[q + 2] + b.z;
        r[q + 3] = acc[q + 3] + b.w;
    }
    #pragma unroll
    for (int q = 0; q < VEC; q++) r[q] = (r[q] > 0.f) ? r[q] : GCN_SLOPE * r[q];

    if (HALF_OUT) {
        __half* rp = outa + (size_t)row * D;
        #pragma unroll
        for (int q = 0; q < VEC; q += 2)
            *(__half2*)(rp + lanecol + q) = __floats2half2_rn(r[q], r[q + 1]);
    } else {
        float* o = outf + (size_t)row * D + lanecol;
        #pragma unroll
        for (int q = 0; q < VEC; q += 4)
            *(float4*)(o + q) = make_float4(r[q], r[q + 1], r[q + 2], r[q + 3]);
    }
}

// ---------------- launch ----------------
extern "C" void kernel_launch(void* const* d_in, const int* in_sizes, int n_in,
                              void* d_out, int out_size) {
    const float* x    = (const float*)d_in[0];
    const int*   rows = (const int*)  d_in[1];
    const int*   cols = (const int*)  d_in[2];
    const float* vals = (const float*)d_in[3];
    const float* W1   = (const float*)d_in[4];
    const float* b1   = (const float*)d_in[5];
    const float* W2   = (const float*)d_in[6];
    const float* b2   = (const float*)d_in[7];
    const float* W3   = (const float*)d_in[8];
    const float* b3   = (const float*)d_in[9];
    float* out = (float*)d_out;

    const int N = GCN_N;
    const int NNZ = GCN_NNZ;
    const int NBLK = (N + 255) / 256;   // 391

    int *rowptr, *cursor, *cnt, *bsum;
    uint2* scv;
    __half *supA, *supB, *ap, *bp1, *bp2, *bp3;
    cudaGetSymbolAddress((void**)&rowptr, g_rowptr);
    cudaGetSymbolAddress((void**)&cursor, g_cursor);
    cudaGetSymbolAddress((void**)&cnt,    g_cnt);
    cudaGetSymbolAddress((void**)&bsum,   g_bsum);
    cudaGetSymbolAddress((void**)&scv,    g_scv);
    cudaGetSymbolAddress((void**)&supA,   g_supA);
    cudaGetSymbolAddress((void**)&supB,   g_supB);
    cudaGetSymbolAddress((void**)&ap,     g_a);
    cudaGetSymbolAddress((void**)&bp1,    g_b1);
    cudaGetSymbolAddress((void**)&bp2,    g_b2);
    cudaGetSymbolAddress((void**)&bp3,    g_b3);

    const int SMEM_GEMM = 3 * (128 * 64 * 2) * 2;   // 96KB
    cudaFuncSetAttribute(gemm_mma, cudaFuncAttributeMaxDynamicSharedMemorySize, SMEM_GEMM);

    // one-time host resources
    static cudaStream_t s2 = nullptr, s3 = nullptr;
    static cudaEvent_t ev_fork, ev_csr, ev_w;
    static cudaEvent_t ev_conv[4], ev_s1[4], ev_g2[4], ev_s2e[4], ev_g3[4];
    if (s2 == nullptr) {
        cudaStreamCreateWithFlags(&s2, cudaStreamNonBlocking);
        cudaStreamCreateWithFlags(&s3, cudaStreamNonBlocking);
        cudaEventCreateWithFlags(&ev_fork, cudaEventDisableTiming);
        cudaEventCreateWithFlags(&ev_csr, cudaEventDisableTiming);
        cudaEventCreateWithFlags(&ev_w, cudaEventDisableTiming);
        for (int i = 0; i < 4; i++) {
            cudaEventCreateWithFlags(&ev_conv[i], cudaEventDisableTiming);
            cudaEventCreateWithFlags(&ev_s1[i], cudaEventDisableTiming);
            cudaEventCreateWithFlags(&ev_g2[i], cudaEventDisableTiming);
            cudaEventCreateWithFlags(&ev_s2e[i], cudaEventDisableTiming);
            cudaEventCreateWithFlags(&ev_g3[i], cudaEventDisableTiming);
        }
    }

    int cst[5] = {0, CH, 2 * CH, 3 * CH, N};   // chunk starts

    // fork
    cudaEventRecord(ev_fork, 0);
    cudaStreamWaitEvent(s2, ev_fork, 0);
    cudaStreamWaitEvent(s3, ev_fork, 0);

    // ---- s3: convert_x chunks ----
    for (int i = 0; i < 4; i++) {
        int r = cst[i + 1] - cst[i];
        convert_x<<<(r * 128 + 255) / 256, 256, 0, s3>>>(
            x + (size_t)cst[i] * 512, ap + (size_t)cst[i] * 512, r * 128);
        cudaEventRecord(ev_conv[i], s3);
    }

    // ---- s2: CSR chain ----
    zero_kernel<<<NBLK, 256, 0, s2>>>(cnt, N);
    hist_kernel<<<(NNZ + 255) / 256, 256, 0, s2>>>(rows, cnt, NNZ);
    scanA_kernel<<<NBLK, 256, 0, s2>>>(cnt, rowptr, bsum, N);
    scanB_kernel<<<1, 512, 0, s2>>>(bsum, NBLK);
    scanC_kernel<<<NBLK, 256, 0, s2>>>(cnt, bsum, rowptr, cursor, N);
    scatter_kernel<<<(NNZ + 255) / 256, 256, 0, s2>>>(rows, cols, vals, cursor, scv, NNZ);
    cudaEventRecord(ev_csr, s2);

    // ---- main: weights, then gemm1 chunks after their converts ----
    wsplit_single<<<(512 * 256 + 255) / 256, 256>>>(W1, bp1, 512, 256);
    wsplit_single<<<(256 * 256 + 255) / 256, 256>>>(W2, bp2, 256, 256);
    wsplit_single<<<(256 * 128 + 255) / 256, 256>>>(W3, bp3, 256, 128);
    cudaEventRecord(ev_w, 0);

    for (int i = 0; i < 4; i++) {
        int r = cst[i + 1] - cst[i];
        cudaStreamWaitEvent(0, ev_conv[i], 0);
        gemm_mma<<<dim3(2, (r + 127) / 128), 256, SMEM_GEMM>>>(
            ap + (size_t)cst[i] * 512, bp1, supA + (size_t)cst[i] * 256, r, 256, 512);
    }

    // ---- layer 1 SpMM chunks (main), gemm2 chunks (s3) ----
    cudaStreamWaitEvent(0, ev_csr, 0);
    for (int i = 0; i < 4; i++) {
        int r = cst[i + 1] - cst[i];
        spmm_kernel<256, true><<<(r + 7) / 8, 256>>>(
            supA, scv, rowptr, b1, nullptr, ap, cst[i], r);
        cudaEventRecord(ev_s1[i], 0);
    }
    cudaStreamWaitEvent(s3, ev_w, 0);
    for (int i = 0; i < 4; i++) {
        int r = cst[i + 1] - cst[i];
        cudaStreamWaitEvent(s3, ev_s1[i], 0);
        gemm_mma<<<dim3(2, (r + 127) / 128), 256, SMEM_GEMM, s3>>>(
            ap + (size_t)cst[i] * 256, bp2, supB + (size_t)cst[i] * 256, r, 256, 256);
        cudaEventRecord(ev_g2[i], s3);
    }

    // ---- layer 2 SpMM chunks (main), gemm3 chunks (s3) ----
    for (int i = 0; i < 4; i++) cudaStreamWaitEvent(0, ev_g2[i], 0);
    for (int i = 0; i < 4; i++) {
        int r = cst[i + 1] - cst[i];
        spmm_kernel<256, true><<<(r + 7) / 8, 256>>>(
            supB, scv, rowptr, b2, nullptr, ap, cst[i], r);
        cudaEventRecord(ev_s2e[i], 0);
    }
    for (int i = 0; i < 4; i++) {
        int r = cst[i + 1] - cst[i];
        cudaStreamWaitEvent(s3, ev_s2e[i], 0);
        gemm_mma<<<dim3(1, (r + 127) / 128), 256, SMEM_GEMM, s3>>>(
            ap + (size_t)cst[i] * 256, bp3, supA + (size_t)cst[i] * 128, r, 128, 256);
        cudaEventRecord(ev_g3[i], s3);
    }

    // ---- layer 3 SpMM (main) -> out ----
    for (int i = 0; i < 4; i++) cudaStreamWaitEvent(0, ev_g3[i], 0);
    spmm_kernel<128, false><<<(N + 7) / 8, 256>>>(
        supA, scv, rowptr, b3, out, nullptr, 0, N);
}

// round 13
// speedup vs baseline: 1.1169x; 1.1169x over previous
#include <cuda_runtime.h>
#include <cuda_fp16.h>
#include <cstdint>

#define GCN_N     100000
#define GCN_NNZ   3200000
#define GCN_SLOPE 0.25f

// ---------------- device scratch (static, allocation-free) ----------------
__device__ __align__(16) int    g_rowptr[GCN_N + 1];
__device__ __align__(16) int    g_cursor[GCN_N];
__device__ __align__(16) int    g_cnt[GCN_N];
__device__ __align__(16) int    g_bsum[512];
__device__ __align__(16) uint2  g_scv[GCN_NNZ];                // packed (col, val)
__device__ __align__(16) __half g_sup [(size_t)GCN_N * 256];   // GEMM output fp16
__device__ __align__(16) __half g_a[(size_t)GCN_N * 512];      // activations fp16
__device__ __align__(16) __half g_b1[256 * 512];               // W1^T fp16
__device__ __align__(16) __half g_b2[256 * 256];               // W2^T fp16
__device__ __align__(16) __half g_b3[128 * 256];               // W3^T fp16

// ---------------- CSR build ----------------
__global__ void zero_kernel(int* p, int n) {
    int i = blockIdx.x * blockDim.x + threadIdx.x;
    if (i < n) p[i] = 0;
}
__global__ void hist_kernel(const int* __restrict__ rows, int* __restrict__ counts, int nnz) {
    int i = blockIdx.x * blockDim.x + threadIdx.x;
    if (i < nnz) atomicAdd(&counts[rows[i]], 1);
}
__global__ void scanA_kernel(const int* __restrict__ counts, int* __restrict__ rowptr,
                             int* __restrict__ bsum, int n) {
    __shared__ int ws[8];
    int i = blockIdx.x * 256 + threadIdx.x;
    int lane = threadIdx.x & 31, w = threadIdx.x >> 5;
    int v = (i < n) ? counts[i] : 0;
    int x = v;
    #pragma unroll
    for (int d = 1; d < 32; d <<= 1) {
        int y = __shfl_up_sync(0xffffffffu, x, d);
        if (lane >= d) x += y;
    }
    if (lane == 31) ws[w] = x;
    __syncthreads();
    if (w == 0) {
        int t = (lane < 8) ? ws[lane] : 0;
        #pragma unroll
        for (int d = 1; d < 8; d <<= 1) {
            int y = __shfl_up_sync(0xffffffffu, t, d);
            if (lane >= d) t += y;
        }
        if (lane < 8) ws[lane] = t;
    }
    __syncthreads();
    int incl = x + (w > 0 ? ws[w - 1] : 0);
    if (i < n) rowptr[i + 1] = incl;
    if (threadIdx.x == 255) bsum[blockIdx.x] = incl;
}
__global__ void scanB_kernel(int* __restrict__ bsum, int nb) {
    __shared__ int ws[16];
    int i = threadIdx.x, lane = i & 31, w = i >> 5;
    int v = (i < nb) ? bsum[i] : 0;
    int x = v;
    #pragma unroll
    for (int d = 1; d < 32; d <<= 1) {
        int y = __shfl_up_sync(0xffffffffu, x, d);
        if (lane >= d) x += y;
    }
    if (lane == 31) ws[w] = x;
    __syncthreads();
    if (w == 0) {
        int t = (lane < 16) ? ws[lane] : 0;
        #pragma unroll
        for (int d = 1; d < 16; d <<= 1) {
            int y = __shfl_up_sync(0xffffffffu, t, d);
            if (lane >= d) t += y;
        }
        if (lane < 16) ws[lane] = t;
    }
    __syncthreads();
    int incl = x + (w > 0 ? ws[w - 1] : 0);
    if (i < nb) bsum[i] = incl - v;
}
__global__ void scanC_kernel(const int* __restrict__ counts, const int* __restrict__ bsum,
                             int* __restrict__ rowptr, int* __restrict__ cursor, int n) {
    int i = blockIdx.x * 256 + threadIdx.x;
    if (i < n) {
        int incl = rowptr[i + 1] + bsum[blockIdx.x];
        rowptr[i + 1] = incl;
        cursor[i] = incl - counts[i];
    }
    if (i == 0) rowptr[0] = 0;
}
__global__ void scatter_kernel(const int* __restrict__ rows, const int* __restrict__ cols,
                               const float* __restrict__ vals, int* __restrict__ cursor,
                               uint2* __restrict__ scv, int nnz) {
    int i = blockIdx.x * blockDim.x + threadIdx.x;
    if (i < nnz) {
        int r = rows[i];
        int pos = atomicAdd(&cursor[r], 1);
        scv[pos] = make_uint2((unsigned)cols[i], __float_as_uint(vals[i]));
    }
}

// x fp32 -> fp16, 8 floats per thread (2x LDG.128, 1x STG.128)
__global__ void convert_x(const float* __restrict__ in, __half* __restrict__ outh, int n8) {
    int i = blockIdx.x * blockDim.x + threadIdx.x;
    if (i >= n8) return;
    float4 a = __ldg((const float4*)in + 2 * i);
    float4 b = __ldg((const float4*)in + 2 * i + 1);
    __half2 h[4] = {__floats2half2_rn(a.x, a.y), __floats2half2_rn(a.z, a.w),
                    __floats2half2_rn(b.x, b.y), __floats2half2_rn(b.z, b.w)};
    ((uint4*)outh)[i] = *(uint4*)h;
}

// W[K,N] -> B[N,K] fp16, tiled transpose (coalesced read + write)
// grid: (N/32, K/32), block: 32x8
__global__ void wsplit_t(const float* __restrict__ W, __half* __restrict__ bp,
                         int K, int N) {
    __shared__ __half tile[32][33];
    int n0 = blockIdx.x * 32, k0 = blockIdx.y * 32;
    int tx = threadIdx.x, ty = threadIdx.y;
    #pragma unroll
    for (int j = 0; j < 4; j++) {
        int k = k0 + ty + j * 8;
        tile[ty + j * 8][tx] = __float2half_rn(W[(size_t)k * N + n0 + tx]);
    }
    __syncthreads();
    #pragma unroll
    for (int j = 0; j < 4; j++) {
        int n = n0 + ty + j * 8;
        bp[(size_t)n * K + k0 + tx] = tile[tx][ty + j * 8];
    }
}

// ---------------- fp16 GEMM via mma.sync, cp.async -------------------------
__global__ __launch_bounds__(256) void gemm_mma(const __half* __restrict__ A,
                                                const __half* __restrict__ B,
                                                __half* __restrict__ C,
                                                int M, int N, int K) {
    extern __shared__ char smem[];
    constexpr int STAGES = 3;
    constexpr int ABYTES = 128 * 64 * 2;
    constexpr int BBYTES = 128 * 64 * 2;
    uint32_t sa_base;
    asm("{ .reg .u64 t; cvta.to.shared.u64 t, %1; cvt.u32.u64 %0, t; }" : "=r"(sa_base) : "l"(smem));
    uint32_t sb_base = sa_base + STAGES * ABYTES;

    int tid = threadIdx.x;
    int wid = tid >> 5, lane = tid & 31;
    int wm = wid & 3, wn = wid >> 2;
    int m0 = blockIdx.y * 128, n0 = blockIdx.x * 128;
    int NC = K / 64;

    float d[2][8][4];
    #pragma unroll
    for (int mi = 0; mi < 2; mi++)
        #pragma unroll
        for (int nj = 0; nj < 8; nj++)
            #pragma unroll
            for (int q = 0; q < 4; q++) d[mi][nj][q] = 0.f;

    const __half* Abase = A + (size_t)m0 * K;
    const __half* Bbase = B + (size_t)n0 * K;

#define LOAD_STAGE(st, ch) do {                                                   \
        uint32_t _da = sa_base + (st) * ABYTES;                                   \
        uint32_t _db = sb_base + (st) * BBYTES;                                   \
        int _k0 = (ch) * 64;                                                      \
        _Pragma("unroll")                                                         \
        for (int _i = 0; _i < 4; _i++) {                                          \
            int _u = tid + _i * 256;                                              \
            int _r = _u >> 3, _c = _u & 7;                                        \
            uint32_t _off = (uint32_t)(_r * 128 + _c * 16);                       \
            _off ^= ((_off >> 3) & 0x70);                                         \
            const __half* _src = Abase + (size_t)_r * K + _k0 + _c * 8;           \
            uint32_t _sz = (m0 + _r < M) ? 16u : 0u;                              \
            if (m0 + _r >= M) _src = Abase + _k0;                                 \
            asm volatile("cp.async.cg.shared.global [%0], [%1], 16, %2;"          \
                :: "r"(_da + _off), "l"(_src), "r"(_sz));                         \
        }                                                                         \
        _Pragma("unroll")                                                         \
        for (int _i = 0; _i < 4; _i++) {                                          \
            int _u = tid + _i * 256;                                              \
            int _r = _u >> 3, _c = _u & 7;                                        \
            uint32_t _off = (uint32_t)(_r * 128 + _c * 16);                       \
            _off ^= ((_off >> 3) & 0x70);                                         \
            const __half* _src = Bbase + (size_t)_r * K + _k0 + _c * 8;           \
            asm volatile("cp.async.cg.shared.global [%0], [%1], 16;"              \
                :: "r"(_db + _off), "l"(_src));                                   \
        }                                                                         \
    } while (0)

    LOAD_STAGE(0, 0);
    asm volatile("cp.async.commit_group;");
    if (NC > 1) LOAD_STAGE(1, 1);
    asm volatile("cp.async.commit_group;");

    for (int c = 0; c < NC; c++) {
        asm volatile("cp.async.wait_group 1;");
        __syncthreads();
        if (c + 2 < NC) LOAD_STAGE((c + 2) % STAGES, c + 2);
        asm volatile("cp.async.commit_group;");

        uint32_t da = sa_base + (c % STAGES) * ABYTES;
        uint32_t db = sb_base + (c % STAGES) * BBYTES;
        #pragma unroll
        for (int kk = 0; kk < 4; kk++) {
            int k16 = kk * 16;
            uint32_t a[2][4];
            #pragma unroll
            for (int mi = 0; mi < 2; mi++) {
                int row = wm * 32 + mi * 16 + (lane & 15);
                int colB = (k16 + ((lane >> 4) << 3)) * 2;
                uint32_t off = (uint32_t)(row * 128 + colB);
                off ^= ((off >> 3) & 0x70);
                asm volatile("ldmatrix.sync.aligned.m8n8.x4.shared.b16 {%0,%1,%2,%3}, [%4];"
                    : "=r"(a[mi][0]), "=r"(a[mi][1]), "=r"(a[mi][2]), "=r"(a[mi][3])
                    : "r"(da + off));
            }
            uint32_t b[8][2];
            #pragma unroll
            for (int nj = 0; nj < 4; nj++) {
                int nrow = wn * 64 + nj * 16 + (lane & 7) + ((lane >> 4) << 3);
                int colB = (k16 + (((lane >> 3) & 1) << 3)) * 2;
                uint32_t off = (uint32_t)(nrow * 128 + colB);
                off ^= ((off >> 3) & 0x70);
                uint32_t r0, r1, r2, r3;
                asm volatile("ldmatrix.sync.aligned.m8n8.x4.shared.b16 {%0,%1,%2,%3}, [%4];"
                    : "=r"(r0), "=r"(r1), "=r"(r2), "=r"(r3) : "r"(db + off));
                b[nj * 2][0] = r0; b[nj * 2][1] = r1;
                b[nj * 2 + 1][0] = r2; b[nj * 2 + 1][1] = r3;
            }
            #pragma unroll
            for (int mi = 0; mi < 2; mi++)
                #pragma unroll
                for (int nj = 0; nj < 8; nj++)
                    asm volatile("mma.sync.aligned.m16n8k16.row.col.f32.f16.f16.f32 "
                        "{%0,%1,%2,%3}, {%4,%5,%6,%7}, {%8,%9}, {%0,%1,%2,%3};"
                        : "+f"(d[mi][nj][0]), "+f"(d[mi][nj][1]),
                          "+f"(d[mi][nj][2]), "+f"(d[mi][nj][3])
                        : "r"(a[mi][0]), "r"(a[mi][1]), "r"(a[mi][2]), "r"(a[mi][3]),
                          "r"(b[nj][0]), "r"(b[nj][1]));
        }
        __syncthreads();
    }
#undef LOAD_STAGE

    #pragma unroll
    for (int mi = 0; mi < 2; mi++) {
        int r0 = m0 + wm * 32 + mi * 16 + (lane >> 2);
        #pragma unroll
        for (int nj = 0; nj < 8; nj++) {
            int col = n0 + wn * 64 + nj * 8 + 2 * (lane & 3);
            if (r0 < M)
                *(__half2*)(C + (size_t)r0 * N + col) =
                    __floats2half2_rn(d[mi][nj][0], d[mi][nj][1]);
            if (r0 + 8 < M)
                *(__half2*)(C + (size_t)(r0 + 8) * N + col) =
                    __floats2half2_rn(d[mi][nj][2], d[mi][nj][3]);
        }
    }
}

// ---------------- SpMM (fp16 gather, packed edges) + bias + leaky ----------
template <int D, bool HALF_OUT>
__global__ __launch_bounds__(256) void spmm_kernel(const __half* __restrict__ sup,
                                                   const uint2* __restrict__ scv,
                                                   const int* __restrict__ rowptr,
                                                   const float* __restrict__ bias,
                                                   float* __restrict__ outf,
                                                   __half* __restrict__ outa,
                                                   int n) {
    int warp = (blockIdx.x * blockDim.x + threadIdx.x) >> 5;
    int lane = threadIdx.x & 31;
    if (warp >= n) return;
    int s = rowptr[warp];
    int e = rowptr[warp + 1];
    constexpr int VEC = D / 32;
    float acc[VEC];
    #pragma unroll
    for (int q = 0; q < VEC; q++) acc[q] = 0.f;

    const int lanecol = lane * VEC;

#define GATHER(cc, vv) do {                                                        \
        const __half* _b = sup + (size_t)(cc) * D + lanecol;                       \
        if (VEC == 8) {                                                            \
            uint4 _r = __ldg((const uint4*)_b);                                    \
            const __half2* _h = (const __half2*)&_r;                               \
            _Pragma("unroll")                                                      \
            for (int _q = 0; _q < 4; _q++) {                                       \
                float2 _f = __half22float2(_h[_q]);                                \
                acc[2 * _q]     += (vv) * _f.x;                                    \
                acc[2 * _q + 1] += (vv) * _f.y;                                    \
            }                                                                      \
        } else {                                                                   \
            uint2 _r = __ldg((const uint2*)_b);                                    \
            const __half2* _h = (const __half2*)&_r;                               \
            _Pragma("unroll")                                                      \
            for (int _q = 0; _q < 2; _q++) {                                       \
                float2 _f = __half22float2(_h[_q]);                                \
                acc[2 * _q]     += (vv) * _f.x;                                    \
                acc[2 * _q + 1] += (vv) * _f.y;                                    \
            }                                                                      \
        }                                                                          \
    } while (0)

    int p = s;
    for (; p + 3 < e; p += 4) {
        uint2 e0 = __ldg(&scv[p]),     e1 = __ldg(&scv[p + 1]);
        uint2 e2 = __ldg(&scv[p + 2]), e3 = __ldg(&scv[p + 3]);
        GATHER(e0.x, __uint_as_float(e0.y));
        GATHER(e1.x, __uint_as_float(e1.y));
        GATHER(e2.x, __uint_as_float(e2.y));
        GATHER(e3.x, __uint_as_float(e3.y));
    }
    for (; p < e; p++) {
        uint2 ee = __ldg(&scv[p]);
        GATHER(ee.x, __uint_as_float(ee.y));
    }
#undef GATHER

    float r[VEC];
    #pragma unroll
    for (int q = 0; q < VEC; q += 4) {
        float4 b = __ldg((const float4*)(bias + lanecol + q));
        r[q]     = acc[q]     + b.x;
        r[q + 1] = acc[q + 1] + b.y;
        r[q + 2] = acc[q + 2] + b.z;
        r[q + 3] = acc[q + 3] + b.w;
    }
    #pragma unroll
    for (int q = 0; q < VEC; q++) r[q] = (r[q] > 0.f) ? r[q] : GCN_SLOPE * r[q];

    if (HALF_OUT) {
        __half* rp = outa + (size_t)warp * D;
        #pragma unroll
        for (int q = 0; q < VEC; q += 2)
            *(__half2*)(rp + lanecol + q) = __floats2half2_rn(r[q], r[q + 1]);
    } else {
        float* o = outf + (size_t)warp * D + lanecol;
        #pragma unroll
        for (int q = 0; q < VEC; q += 4)
            *(float4*)(o + q) = make_float4(r[q], r[q + 1], r[q + 2], r[q + 3]);
    }
}

// ---------------- launch ----------------
extern "C" void kernel_launch(void* const* d_in, const int* in_sizes, int n_in,
                              void* d_out, int out_size) {
    const float* x    = (const float*)d_in[0];
    const int*   rows = (const int*)  d_in[1];
    const int*   cols = (const int*)  d_in[2];
    const float* vals = (const float*)d_in[3];
    const float* W1   = (const float*)d_in[4];
    const float* b1   = (const float*)d_in[5];
    const float* W2   = (const float*)d_in[6];
    const float* b2   = (const float*)d_in[7];
    const float* W3   = (const float*)d_in[8];
    const float* b3   = (const float*)d_in[9];
    float* out = (float*)d_out;

    const int N = GCN_N;
    const int NNZ = GCN_NNZ;
    const int NBLK = (N + 255) / 256;   // 391

    int *rowptr, *cursor, *cnt, *bsum;
    uint2* scv;
    __half *sup, *ap, *bp1, *bp2, *bp3;
    cudaGetSymbolAddress((void**)&rowptr, g_rowptr);
    cudaGetSymbolAddress((void**)&cursor, g_cursor);
    cudaGetSymbolAddress((void**)&cnt,    g_cnt);
    cudaGetSymbolAddress((void**)&bsum,   g_bsum);
    cudaGetSymbolAddress((void**)&scv,    g_scv);
    cudaGetSymbolAddress((void**)&sup,    g_sup);
    cudaGetSymbolAddress((void**)&ap,     g_a);
    cudaGetSymbolAddress((void**)&bp1,    g_b1);
    cudaGetSymbolAddress((void**)&bp2,    g_b2);
    cudaGetSymbolAddress((void**)&bp3,    g_b3);

    const int SMEM_GEMM = 3 * (128 * 64 * 2) * 2;   // 96KB
    cudaFuncSetAttribute(gemm_mma, cudaFuncAttributeMaxDynamicSharedMemorySize, SMEM_GEMM);

    // one-time host resources (identical captured work every call)
    static cudaStream_t s2 = nullptr;
    static cudaEvent_t e_fork = nullptr, e_csr = nullptr;
    if (s2 == nullptr) {
        cudaStreamCreateWithFlags(&s2, cudaStreamNonBlocking);
        cudaEventCreateWithFlags(&e_fork, cudaEventDisableTiming);
        cudaEventCreateWithFlags(&e_csr, cudaEventDisableTiming);
    }

    const int MT128 = (N + 127) / 128;   // 782
    int spmm_grid = (N + 7) / 8;

    // fork: CSR chain on side stream, GEMM path on main stream
    cudaEventRecord(e_fork, 0);
    cudaStreamWaitEvent(s2, e_fork, 0);

    // ---- side stream: CSR build ----
    zero_kernel<<<NBLK, 256, 0, s2>>>(cnt, N);
    hist_kernel<<<(NNZ + 255) / 256, 256, 0, s2>>>(rows, cnt, NNZ);
    scanA_kernel<<<NBLK, 256, 0, s2>>>(cnt, rowptr, bsum, N);
    scanB_kernel<<<1, 512, 0, s2>>>(bsum, NBLK);
    scanC_kernel<<<NBLK, 256, 0, s2>>>(cnt, bsum, rowptr, cursor, N);
    scatter_kernel<<<(NNZ + 255) / 256, 256, 0, s2>>>(rows, cols, vals, cursor, scv, NNZ);
    cudaEventRecord(e_csr, s2);

    // ---- main stream: conversions + layer-1 GEMM ----
    wsplit_t<<<dim3(256 / 32, 512 / 32), dim3(32, 8)>>>(W1, bp1, 512, 256);
    convert_x<<<(N * 512 / 8 + 255) / 256, 256>>>(x, ap, N * 512 / 8);
    wsplit_t<<<dim3(256 / 32, 256 / 32), dim3(32, 8)>>>(W2, bp2, 256, 256);
    wsplit_t<<<dim3(128 / 32, 256 / 32), dim3(32, 8)>>>(W3, bp3, 256, 128);
    gemm_mma<<<dim3(2, MT128), 256, SMEM_GEMM>>>(ap, bp1, sup, N, 256, 512);

    // join: spmm1 needs CSR + gemm1
    cudaStreamWaitEvent(0, e_csr, 0);

    spmm_kernel<256, true><<<spmm_grid, 256>>>(sup, scv, rowptr, b1, nullptr, ap, N);

    gemm_mma<<<dim3(2, MT128), 256, SMEM_GEMM>>>(ap, bp2, sup, N, 256, 256);
    spmm_kernel<256, true><<<spmm_grid, 256>>>(sup, scv, rowptr, b2, nullptr, ap, N);

    gemm_mma<<<dim3(1, MT128), 256, SMEM_GEMM>>>(ap, bp3, sup, N, 128, 256);
    spmm_kernel<128, false><<<spmm_grid, 256>>>(sup, scv, rowptr, b3, out, nullptr, N);
}